// round 14
// baseline (speedup 1.0000x reference)
#include <cuda_runtime.h>
#include <cuda_bf16.h>
#include <cstdint>

// Problem dimensions (fixed by the reference).
#define NW 50000
#define NT 2000
#define ND 50000
#define DO 128
#define DW 256
#define E_MAX 2200000   // total edges = 2.1M; padded

// Concatenated per-(relation,dst) counter layout.
constexpr int DEG_WW = 0;
constexpr int DEG_WT = NW;
constexpr int DEG_TT = NW + NT;
constexpr int DEG_WD = NW + 2 * NT;
constexpr int DEG_TD = NW + 2 * NT + ND;
constexpr int NDEG   = NW + 2 * NT + 2 * ND;   // 154000
constexpr int NSCAN  = (NDEG + 1023) / 1024;   // 151 scan blocks

// Packed-operand geometry.
constexpr int KPW = DW / 2;   // 128 u32 per word-feature row
constexpr int KPT = 64;       // 64 u32 per topic-feature row
// W-pack slot offsets (u32): ww, wt, wd (128x128), tt, td (128x64).
constexpr int WP_WW = 0;
constexpr int WP_WT = 16384;
constexpr int WP_WD = 32768;
constexpr int WP_TT = 49152;
constexpr int WP_TD = 57344;
constexpr int WP_TOTAL = 65536;

// ---------------------------------------------------------------------------
// Scratch (static __device__ arrays — allocation-free per harness rules).
// ---------------------------------------------------------------------------
__device__ float g_Wh_ww[(size_t)NW * DO];
__device__ float g_Wh_wt[(size_t)NW * DO];
__device__ float g_Wh_wd[(size_t)NW * DO];
__device__ float g_Wh_td[(size_t)NT * DO];
__device__ float g_Wh_tt[(size_t)NT * DO];

// Pre-packed split-bf16 operands (hi/lo bf16x2 in u32).
__device__ uint32_t g_Aw_hi[(size_t)NW * KPW];
__device__ uint32_t g_Aw_lo[(size_t)NW * KPW];
__device__ uint32_t g_At_hi[(size_t)NT * KPT];
__device__ uint32_t g_At_lo[(size_t)NT * KPT];
__device__ uint32_t g_Wp_hi[WP_TOTAL];
__device__ uint32_t g_Wp_lo[WP_TOTAL];

__device__ int      g_cnt[NDEG];    // per-(rel,dst) degree
__device__ int      g_cur[NDEG];    // fill cursors for permute
__device__ int      g_off[NDEG];    // exclusive scan of g_cnt (global)
__device__ int      g_bsum[256];    // scan block sums
__device__ int      g_boff[256];    // scanned block sums

__device__ unsigned long long g_edge[E_MAX];  // packed (src | w<<32), dst-grouped

// Edge-set bundle for merged CSR kernels (passed by value).
struct ES {
    const int*   src[5];
    const int*   dst[5];
    const float* w[5];
    int          E[5];
    int          base[5];
};

// ---------------------------------------------------------------------------
// Split-bf16 packing helper.
// ---------------------------------------------------------------------------
__device__ __forceinline__ void split_pack(float x0, float x1,
                                           uint32_t& hi, uint32_t& lo) {
    __nv_bfloat16 h0 = __float2bfloat16(x0);
    __nv_bfloat16 h1 = __float2bfloat16(x1);
    __nv_bfloat16 l0 = __float2bfloat16(x0 - __bfloat162float(h0));
    __nv_bfloat16 l1 = __float2bfloat16(x1 - __bfloat162float(h1));
    hi = (uint32_t)__bfloat16_as_ushort(h0) |
         ((uint32_t)__bfloat16_as_ushort(h1) << 16);
    lo = (uint32_t)__bfloat16_as_ushort(l0) |
         ((uint32_t)__bfloat16_as_ushort(l1) << 16);
}

// ---------------------------------------------------------------------------
// Operand pre-pack kernels (run ONCE; removes per-CTA cvt work from GEMMs).
// conv_A: streaming float2 -> (hi,lo) u32 for word + topic features.
// conv_W: [k][n] -> [n][kp] transpose + split-pack for all 5 weight matrices.
// ---------------------------------------------------------------------------
constexpr int NPAIR_A = NW * KPW + NT * KPT;

__global__ __launch_bounds__(256)
void conv_A(const float* __restrict__ fw, const float* __restrict__ ft) {
    int i = blockIdx.x * blockDim.x + threadIdx.x;
    if (i < NW * KPW) {
        float2 v = *(const float2*)(fw + 2 * (size_t)i);
        uint32_t hi, lo;
        split_pack(v.x, v.y, hi, lo);
        g_Aw_hi[i] = hi; g_Aw_lo[i] = lo;
    } else if (i < NPAIR_A) {
        int j = i - NW * KPW;
        float2 v = *(const float2*)(ft + 2 * (size_t)j);
        uint32_t hi, lo;
        split_pack(v.x, v.y, hi, lo);
        g_At_hi[j] = hi; g_At_lo[j] = lo;
    }
}

struct WS {
    const float* W[5];
    int kp[5];     // u32 per n-row (DIN/2)
    int base[5];   // slot offset in g_Wp_*
};

__global__ __launch_bounds__(256)
void conv_W(WS ws) {
    int i = blockIdx.x * blockDim.x + threadIdx.x;
#pragma unroll
    for (int r = 0; r < 5; r++) {
        int n_elem = DO * ws.kp[r];
        if (i < n_elem) {
            int n  = i / ws.kp[r];
            int kp = i % ws.kp[r];
            float a = ws.W[r][(size_t)(2 * kp)     * DO + n];
            float b = ws.W[r][(size_t)(2 * kp + 1) * DO + n];
            uint32_t hi, lo;
            split_pack(a, b, hi, lo);
            g_Wp_hi[ws.base[r] + i] = hi;
            g_Wp_lo[ws.base[r] + i] = lo;
            return;
        }
        i -= n_elem;
    }
}

// ---------------------------------------------------------------------------
// CSR build: zero counters -> merged histogram -> 3-phase scan -> merged
// permute (packed 8-byte edge payloads).
// ---------------------------------------------------------------------------
__global__ void zero_cnt() {
    int i = blockIdx.x * blockDim.x + threadIdx.x;
    if (i < NDEG) { g_cnt[i] = 0; g_cur[i] = 0; }
}

__global__ __launch_bounds__(256)
void hist_all(ES es, int total) {
    int i = blockIdx.x * blockDim.x + threadIdx.x;
    if (i >= total) return;
    int e = i;
#pragma unroll
    for (int r = 0; r < 5; r++) {
        if (e < es.E[r]) {
            atomicAdd(&g_cnt[es.base[r] + es.dst[r][e]], 1);
            return;
        }
        e -= es.E[r];
    }
}

__global__ __launch_bounds__(256)
void scan1() {
    __shared__ int sh[256];
    int t    = threadIdx.x;
    int base = blockIdx.x * 1024 + t * 4;
    int v[4];
#pragma unroll
    for (int j = 0; j < 4; j++)
        v[j] = (base + j < NDEG) ? g_cnt[base + j] : 0;
    int tsum = v[0] + v[1] + v[2] + v[3];
    sh[t] = tsum;
    __syncthreads();
    for (int d = 1; d < 256; d <<= 1) {
        int x = (t >= d) ? sh[t - d] : 0;
        __syncthreads();
        sh[t] += x;
        __syncthreads();
    }
    int run = sh[t] - tsum;
#pragma unroll
    for (int j = 0; j < 4; j++) {
        if (base + j < NDEG) g_off[base + j] = run;
        run += v[j];
    }
    if (t == 255) g_bsum[blockIdx.x] = sh[255];
}

__global__ __launch_bounds__(256)
void scan2() {
    __shared__ int sh[256];
    int t = threadIdx.x;
    int v = (t < NSCAN) ? g_bsum[t] : 0;
    sh[t] = v;
    __syncthreads();
    for (int d = 1; d < 256; d <<= 1) {
        int x = (t >= d) ? sh[t - d] : 0;
        __syncthreads();
        sh[t] += x;
        __syncthreads();
    }
    g_boff[t] = sh[t] - v;
}

__global__ __launch_bounds__(256)
void scan3() {
    int i = blockIdx.x * blockDim.x + threadIdx.x;
    if (i < NDEG) g_off[i] += g_boff[i >> 10];
}

__global__ __launch_bounds__(256)
void permute_all(ES es, int total) {
    int i = blockIdx.x * blockDim.x + threadIdx.x;
    if (i >= total) return;
    int e = i;
#pragma unroll
    for (int r = 0; r < 5; r++) {
        if (e < es.E[r]) {
            int d   = es.base[r] + es.dst[r][e];
            int pos = g_off[d] + atomicAdd(&g_cur[d], 1);
            unsigned long long p =
                (unsigned long long)(unsigned)es.src[r][e] |
                ((unsigned long long)__float_as_uint(es.w[r][e]) << 32);
            g_edge[pos] = p;
            return;
        }
        e -= es.E[r];
    }
}

// ---------------------------------------------------------------------------
// Split-BF16 tensor-core GEMM on PRE-PACKED operands.
// mma.sync.m16n8k16.bf16, 3-product compensation (fp32-grade accuracy).
// Fill is now 4x LDG.128 + 4x STS.128 per thread per k-tile (conversions and
// the B transpose were hoisted into conv_A / conv_W).
// BM=128, BN=128, BK=16, 256 threads = 8 warps (4 along M x 2 along N).
// Smem row stride 12 u32 (8 used + 4 pad): conflict-free fragment LDS.
// blockIdx.y selects one of three operand sets.
// ---------------------------------------------------------------------------
__device__ __forceinline__ void mma_bf16(float* d, const uint32_t* a,
                                         const uint32_t* b) {
    asm volatile(
        "mma.sync.aligned.m16n8k16.row.col.f32.bf16.bf16.f32 "
        "{%0,%1,%2,%3}, {%4,%5,%6,%7}, {%8,%9}, {%0,%1,%2,%3};"
        : "+f"(d[0]), "+f"(d[1]), "+f"(d[2]), "+f"(d[3])
        : "r"(a[0]), "r"(a[1]), "r"(a[2]), "r"(a[3]), "r"(b[0]), "r"(b[1]));
}

struct GemmArgs {
    const uint32_t* Ah;
    const uint32_t* Al;
    const uint32_t* Wh[3];
    const uint32_t* Wl[3];
    const float*    bias[3];
    float*          C[3];
    int             M;
};

template <int KP>
__global__ __launch_bounds__(256)
void gemm_bf16p(GemmArgs ga) {
    constexpr int S = 12;   // u32 row stride (8 kp used + 4 pad)
    __shared__ uint32_t As_hi[128 * S], As_lo[128 * S];   // [row][kp]
    __shared__ uint32_t Bs_hi[128 * S], Bs_lo[128 * S];   // [n][kp]

    const uint32_t* Wh   = ga.Wh[blockIdx.y];
    const uint32_t* Wl   = ga.Wl[blockIdx.y];
    const float*    bias = ga.bias[blockIdx.y];
    float*          C    = ga.C[blockIdx.y];
    const int       M    = ga.M;

    const int t    = threadIdx.x;
    const int m0   = blockIdx.x * 128;
    const int wid  = t >> 5;
    const int lane = t & 31;
    const int g    = lane >> 2;   // group id  (0..7)
    const int tg   = lane & 3;    // thread-in-group (0..3)
    const int m0w  = (wid & 3) * 32;   // warp M origin
    const int n0w  = (wid >> 2) * 64;  // warp N origin

    const int fr = t >> 1;          // fill row (A) / col n (B): 0..127
    const int fo = (t & 1) * 4;     // kp offset 0 or 4

    float acc[2][8][4];
#pragma unroll
    for (int mt = 0; mt < 2; mt++)
#pragma unroll
        for (int nt = 0; nt < 8; nt++)
#pragma unroll
            for (int j = 0; j < 4; j++) acc[mt][nt][j] = 0.0f;

    for (int k0p = 0; k0p < KP; k0p += 8) {
        // ---- A fill: one uint4 hi + lo. ----
        {
            uint4 ah = make_uint4(0, 0, 0, 0), al = make_uint4(0, 0, 0, 0);
            if (m0 + fr < M) {
                size_t idx = (size_t)(m0 + fr) * KP + k0p + fo;
                ah = *(const uint4*)(ga.Ah + idx);
                al = *(const uint4*)(ga.Al + idx);
            }
            *(uint4*)&As_hi[fr * S + fo] = ah;
            *(uint4*)&As_lo[fr * S + fo] = al;
        }
        // ---- B fill: one uint4 hi + lo (pre-transposed [n][kp]). ----
        {
            size_t idx = (size_t)fr * KP + k0p + fo;
            *(uint4*)&Bs_hi[fr * S + fo] = *(const uint4*)(Wh + idx);
            *(uint4*)&Bs_lo[fr * S + fo] = *(const uint4*)(Wl + idx);
        }
        __syncthreads();

        // ---- One m16n8k16 step covers the 16-wide k tile. ----
        uint32_t a_hi[2][4], a_lo[2][4];
#pragma unroll
        for (int mt = 0; mt < 2; mt++) {
            int r0 = (m0w + mt * 16 + g) * S;
            int r1 = (m0w + mt * 16 + g + 8) * S;
            a_hi[mt][0] = As_hi[r0 + tg];
            a_hi[mt][1] = As_hi[r1 + tg];
            a_hi[mt][2] = As_hi[r0 + tg + 4];
            a_hi[mt][3] = As_hi[r1 + tg + 4];
            a_lo[mt][0] = As_lo[r0 + tg];
            a_lo[mt][1] = As_lo[r1 + tg];
            a_lo[mt][2] = As_lo[r0 + tg + 4];
            a_lo[mt][3] = As_lo[r1 + tg + 4];
        }
#pragma unroll
        for (int nt = 0; nt < 8; nt++) {
            int nb = (n0w + nt * 8 + g) * S;
            uint32_t b_hi[2], b_lo[2];
            b_hi[0] = Bs_hi[nb + tg];
            b_hi[1] = Bs_hi[nb + tg + 4];
            b_lo[0] = Bs_lo[nb + tg];
            b_lo[1] = Bs_lo[nb + tg + 4];
#pragma unroll
            for (int mt = 0; mt < 2; mt++) {
                mma_bf16(acc[mt][nt], a_hi[mt], b_hi);
                mma_bf16(acc[mt][nt], a_lo[mt], b_hi);
                mma_bf16(acc[mt][nt], a_hi[mt], b_lo);
            }
        }
        __syncthreads();
    }

    // Epilogue: bias + store.
#pragma unroll
    for (int nt = 0; nt < 8; nt++) {
        int col = n0w + nt * 8 + 2 * tg;
        float bx = bias[col];
        float by = bias[col + 1];
#pragma unroll
        for (int mt = 0; mt < 2; mt++) {
            int mr = m0 + m0w + mt * 16 + g;
            if (mr < M) {
                float2 o = make_float2(acc[mt][nt][0] + bx,
                                       acc[mt][nt][1] + by);
                *(float2*)(C + (size_t)mr * DO + col) = o;
            }
            if (mr + 8 < M) {
                float2 o = make_float2(acc[mt][nt][2] + bx,
                                       acc[mt][nt][3] + by);
                *(float2*)(C + (size_t)(mr + 8) * DO + col) = o;
            }
        }
    }
}

// ---------------------------------------------------------------------------
// Aggregation (CSR, atomic-free): ONE WARP per dst row, lane owns a float4
// column slice -> one LDG.128 per lane per edge. 2x-unrolled edge loop.
// Mean + cross-etype sum + coalesced float4 output store fused.
// ---------------------------------------------------------------------------
__device__ __forceinline__ float4 mean_row_w(const float* __restrict__ Wh,
                                             int cnt_base, int row, int lane) {
    int beg = g_off[cnt_base + row];
    int deg = g_cnt[cnt_base + row];
    float4 a0 = make_float4(0.f, 0.f, 0.f, 0.f);
    float4 a1 = make_float4(0.f, 0.f, 0.f, 0.f);
    int e = 0;
    for (; e + 2 <= deg; e += 2) {
        unsigned long long pA = g_edge[beg + e];
        unsigned long long pB = g_edge[beg + e + 1];
        int   sA = (int)(unsigned)pA;
        int   sB = (int)(unsigned)pB;
        float wA = __uint_as_float((unsigned)(pA >> 32));
        float wB = __uint_as_float((unsigned)(pB >> 32));
        float4 vA = *(const float4*)(Wh + (size_t)sA * DO + lane * 4);
        float4 vB = *(const float4*)(Wh + (size_t)sB * DO + lane * 4);
        a0.x += wA * vA.x; a0.y += wA * vA.y;
        a0.z += wA * vA.z; a0.w += wA * vA.w;
        a1.x += wB * vB.x; a1.y += wB * vB.y;
        a1.z += wB * vB.z; a1.w += wB * vB.w;
    }
    if (e < deg) {
        unsigned long long p = g_edge[beg + e];
        int   s = (int)(unsigned)p;
        float w = __uint_as_float((unsigned)(p >> 32));
        float4 v = *(const float4*)(Wh + (size_t)s * DO + lane * 4);
        a0.x += w * v.x; a0.y += w * v.y;
        a0.z += w * v.z; a0.w += w * v.w;
    }
    float inv = (deg > 0) ? 1.0f / (float)deg : 0.0f;
    return make_float4((a0.x + a1.x) * inv, (a0.y + a1.y) * inv,
                       (a0.z + a1.z) * inv, (a0.w + a1.w) * inv);
}

__global__ __launch_bounds__(256)
void agg1(const float* __restrict__ Wh, int cnt_base, int out_row0,
          float* __restrict__ out, int nrows) {
    int row  = blockIdx.x * 8 + (threadIdx.x >> 5);
    int lane = threadIdx.x & 31;
    if (row >= nrows) return;
    float4 r = mean_row_w(Wh, cnt_base, row, lane);
    *(float4*)(out + (size_t)(out_row0 + row) * DO + lane * 4) = r;
}

__global__ __launch_bounds__(256)
void agg2(const float* __restrict__ WhA, int baseA,
          const float* __restrict__ WhB, int baseB, int out_row0,
          float* __restrict__ out, int nrows) {
    int row  = blockIdx.x * 8 + (threadIdx.x >> 5);
    int lane = threadIdx.x & 31;
    if (row >= nrows) return;
    float4 rA = mean_row_w(WhA, baseA, row, lane);
    float4 rB = mean_row_w(WhB, baseB, row, lane);
    float4 o  = make_float4(rA.x + rB.x, rA.y + rB.y,
                            rA.z + rB.z, rA.w + rB.w);
    *(float4*)(out + (size_t)(out_row0 + row) * DO + lane * 4) = o;
}

// ---------------------------------------------------------------------------
// Host entry.
// Input order (metadata): 0 feat_word, 1 feat_topic,
//   2-4 ww(src,dst,w), 5-7 wt, 8-10 wd, 11-13 td, 14-16 tt,
//   17/18 W_ww/b_ww, 19/20 W_wt/b_wt, 21/22 W_wd/b_wd, 23/24 W_td/b_td,
//   25/26 W_tt/b_tt
//
// DAG (capture-legal fork):
//   legacy: evFork -> conv_A -> conv_W -> G_words(y=3, evGw)
//           -> G_topics(y=2, evGt) -> [evCSR] agg_doc -> [evS2] join
//   s2:     [evFork] zero_cnt -> hist_all -> scan x3 -> permute_all (evCSR)
//           -> [evGw] agg_word -> [evGt] agg_topic (evS2)
// ---------------------------------------------------------------------------
extern "C" void kernel_launch(void* const* d_in, const int* in_sizes, int n_in,
                              void* d_out, int out_size) {
    static cudaStream_t s2 = nullptr;
    static cudaEvent_t  evFork, evCSR, evGw, evGt, evS2;
    if (s2 == nullptr) {
        cudaStreamCreateWithFlags(&s2, cudaStreamNonBlocking);
        cudaEventCreateWithFlags(&evFork, cudaEventDisableTiming);
        cudaEventCreateWithFlags(&evCSR,  cudaEventDisableTiming);
        cudaEventCreateWithFlags(&evGw,   cudaEventDisableTiming);
        cudaEventCreateWithFlags(&evGt,   cudaEventDisableTiming);
        cudaEventCreateWithFlags(&evS2,   cudaEventDisableTiming);
    }

    const float* feat_word  = (const float*)d_in[0];
    const float* feat_topic = (const float*)d_in[1];

    // Edge sets in CSR order: ww, wt, tt, wd, td.
    ES es;
    es.src[0] = (const int*)d_in[2];  es.dst[0] = (const int*)d_in[3];
    es.w[0] = (const float*)d_in[4];  es.E[0] = in_sizes[2];  es.base[0] = DEG_WW;
    es.src[1] = (const int*)d_in[5];  es.dst[1] = (const int*)d_in[6];
    es.w[1] = (const float*)d_in[7];  es.E[1] = in_sizes[5];  es.base[1] = DEG_WT;
    es.src[2] = (const int*)d_in[14]; es.dst[2] = (const int*)d_in[15];
    es.w[2] = (const float*)d_in[16]; es.E[2] = in_sizes[14]; es.base[2] = DEG_TT;
    es.src[3] = (const int*)d_in[8];  es.dst[3] = (const int*)d_in[9];
    es.w[3] = (const float*)d_in[10]; es.E[3] = in_sizes[8];  es.base[3] = DEG_WD;
    es.src[4] = (const int*)d_in[11]; es.dst[4] = (const int*)d_in[12];
    es.w[4] = (const float*)d_in[13]; es.E[4] = in_sizes[11]; es.base[4] = DEG_TD;
    int totalE = es.E[0] + es.E[1] + es.E[2] + es.E[3] + es.E[4];

    const float* W_ww = (const float*)d_in[17]; const float* b_ww = (const float*)d_in[18];
    const float* W_wt = (const float*)d_in[19]; const float* b_wt = (const float*)d_in[20];
    const float* W_wd = (const float*)d_in[21]; const float* b_wd = (const float*)d_in[22];
    const float* W_td = (const float*)d_in[23]; const float* b_td = (const float*)d_in[24];
    const float* W_tt = (const float*)d_in[25]; const float* b_tt = (const float*)d_in[26];

    float* out = (float*)d_out;

    float* p_ww; cudaGetSymbolAddress((void**)&p_ww, g_Wh_ww);
    float* p_wt; cudaGetSymbolAddress((void**)&p_wt, g_Wh_wt);
    float* p_wd; cudaGetSymbolAddress((void**)&p_wd, g_Wh_wd);
    float* p_td; cudaGetSymbolAddress((void**)&p_td, g_Wh_td);
    float* p_tt; cudaGetSymbolAddress((void**)&p_tt, g_Wh_tt);
    uint32_t* p_Awh; cudaGetSymbolAddress((void**)&p_Awh, g_Aw_hi);
    uint32_t* p_Awl; cudaGetSymbolAddress((void**)&p_Awl, g_Aw_lo);
    uint32_t* p_Ath; cudaGetSymbolAddress((void**)&p_Ath, g_At_hi);
    uint32_t* p_Atl; cudaGetSymbolAddress((void**)&p_Atl, g_At_lo);
    uint32_t* p_Wph; cudaGetSymbolAddress((void**)&p_Wph, g_Wp_hi);
    uint32_t* p_Wpl; cudaGetSymbolAddress((void**)&p_Wpl, g_Wp_lo);

    // ---- Fork s2 from the capture (legacy) stream. ----
    cudaEventRecord(evFork, 0);
    cudaStreamWaitEvent(s2, evFork, 0);

    // ---- s2: CSR build (independent of GEMMs). ----
    zero_cnt<<<(NDEG + 255) / 256, 256, 0, s2>>>();
    hist_all<<<(totalE + 255) / 256, 256, 0, s2>>>(es, totalE);
    scan1<<<NSCAN, 256, 0, s2>>>();
    scan2<<<1, 256, 0, s2>>>();
    scan3<<<(NDEG + 255) / 256, 256, 0, s2>>>();
    permute_all<<<(totalE + 255) / 256, 256, 0, s2>>>(es, totalE);
    cudaEventRecord(evCSR, s2);

    // ---- legacy: operand pre-pack, then projections. ----
    {
        conv_A<<<(NPAIR_A + 255) / 256, 256>>>(feat_word, feat_topic);
        WS ws;
        ws.W[0] = W_ww; ws.kp[0] = KPW; ws.base[0] = WP_WW;
        ws.W[1] = W_wt; ws.kp[1] = KPW; ws.base[1] = WP_WT;
        ws.W[2] = W_wd; ws.kp[2] = KPW; ws.base[2] = WP_WD;
        ws.W[3] = W_tt; ws.kp[3] = KPT; ws.base[3] = WP_TT;
        ws.W[4] = W_td; ws.kp[4] = KPT; ws.base[4] = WP_TD;
        conv_W<<<(WP_TOTAL + 255) / 256, 256>>>(ws);

        GemmArgs gw;
        gw.Ah = p_Awh; gw.Al = p_Awl; gw.M = NW;
        gw.Wh[0] = p_Wph + WP_WW; gw.Wl[0] = p_Wpl + WP_WW;
        gw.Wh[1] = p_Wph + WP_WT; gw.Wl[1] = p_Wpl + WP_WT;
        gw.Wh[2] = p_Wph + WP_WD; gw.Wl[2] = p_Wpl + WP_WD;
        gw.bias[0] = b_ww; gw.bias[1] = b_wt; gw.bias[2] = b_wd;
        gw.C[0] = p_ww; gw.C[1] = p_wt; gw.C[2] = p_wd;
        int gx = (NW + 127) / 128;   // 391 -> y=3: 1173 CTAs
        gemm_bf16p<KPW><<<dim3(gx, 3), 256>>>(gw);
        cudaEventRecord(evGw, 0);

        GemmArgs gt;
        gt.Ah = p_Ath; gt.Al = p_Atl; gt.M = NT;
        gt.Wh[0] = p_Wph + WP_TT; gt.Wl[0] = p_Wpl + WP_TT;
        gt.Wh[1] = p_Wph + WP_TD; gt.Wl[1] = p_Wpl + WP_TD;
        gt.Wh[2] = p_Wph + WP_TD; gt.Wl[2] = p_Wpl + WP_TD;
        gt.bias[0] = b_tt; gt.bias[1] = b_td; gt.bias[2] = b_td;
        gt.C[0] = p_tt; gt.C[1] = p_td; gt.C[2] = p_td;
        int gtx = (NT + 127) / 128;  // 16
        gemm_bf16p<KPT><<<dim3(gtx, 2), 256>>>(gt);
        cudaEventRecord(evGt, 0);
    }

    // ---- s2: aggregates as dependencies resolve (CSR is in-stream). ----
    cudaStreamWaitEvent(s2, evGw, 0);
    agg1<<<(NW + 7) / 8, 256, 0, s2>>>(p_ww, DEG_WW, 0, out, NW);
    cudaStreamWaitEvent(s2, evGt, 0);
    agg2<<<(NT + 7) / 8, 256, 0, s2>>>(p_wt, DEG_WT, p_tt, DEG_TT, NW, out, NT);
    cudaEventRecord(evS2, s2);

    // ---- legacy: doc aggregate (GEMMs in-stream; CSR via event). ----
    cudaStreamWaitEvent(0, evCSR, 0);
    agg2<<<(ND + 7) / 8, 256>>>(p_wd, DEG_WD, p_td, DEG_TD, NW + NT, out, ND);

    // ---- join. ----
    cudaStreamWaitEvent(0, evS2, 0);
}

// round 16
// speedup vs baseline: 1.0993x; 1.0993x over previous
#include <cuda_runtime.h>
#include <cuda_bf16.h>
#include <cstdint>

// Problem dimensions (fixed by the reference).
#define NW 50000
#define NT 2000
#define ND 50000
#define DO 128
#define DW 256
#define E_MAX 2200000   // total edges = 2.1M; padded

// Concatenated per-(relation,dst) counter layout.
constexpr int DEG_WW = 0;
constexpr int DEG_WT = NW;
constexpr int DEG_TT = NW + NT;
constexpr int DEG_WD = NW + 2 * NT;
constexpr int DEG_TD = NW + 2 * NT + ND;
constexpr int NDEG   = NW + 2 * NT + 2 * ND;   // 154000
constexpr int NSCAN  = (NDEG + 1023) / 1024;   // 151 scan blocks

// ---------------------------------------------------------------------------
// Scratch (static __device__ arrays — allocation-free per harness rules).
// ---------------------------------------------------------------------------
__device__ float g_Wh_ww[(size_t)NW * DO];
__device__ float g_Wh_wt[(size_t)NW * DO];
__device__ float g_Wh_wd[(size_t)NW * DO];
__device__ float g_Wh_td[(size_t)NT * DO];
__device__ float g_Wh_tt[(size_t)NT * DO];

__device__ int      g_cnt[NDEG];    // per-(rel,dst) degree
__device__ int      g_cur[NDEG];    // fill cursors for permute
__device__ int      g_off[NDEG];    // exclusive scan of g_cnt (global)
__device__ int      g_bsum[256];    // scan block sums
__device__ int      g_boff[256];    // scanned block sums

__device__ unsigned long long g_edge[E_MAX];  // packed (src | w<<32), dst-grouped

// Edge-set bundle for merged CSR kernels (passed by value).
struct ES {
    const int*   src[5];
    const int*   dst[5];
    const float* w[5];
    int          E[5];
    int          base[5];
};

// ---------------------------------------------------------------------------
// CSR build. hist/permute are 4-edge-per-thread batched: the 4 index loads
// are issued independently BEFORE any atomic (MLP=4 instead of 1).
// CRITICAL guard: threads t >= stride must exit — otherwise the grid's
// round-up threads re-process edges t + k*stride (the R15 duplication bug).
// ---------------------------------------------------------------------------
__global__ void zero_cnt() {
    int i = blockIdx.x * blockDim.x + threadIdx.x;
    if (i < NDEG) { g_cnt[i] = 0; g_cur[i] = 0; }
}

__device__ __forceinline__ int decode_counter(const ES& es, int e, int* rel,
                                              int* idx) {
#pragma unroll
    for (int r = 0; r < 5; r++) {
        if (e < es.E[r]) { *rel = r; *idx = e; return 1; }
        e -= es.E[r];
    }
    return 0;
}

__global__ __launch_bounds__(256)
void hist_all(ES es, int total, int stride) {
    int t = blockIdx.x * blockDim.x + threadIdx.x;
    if (t >= stride) return;              // <- duplication guard
    int d[4]; bool ok[4];
#pragma unroll
    for (int k = 0; k < 4; k++) {
        int e = t + k * stride;
        ok[k] = false;
        if (e < total) {
            int r, idx;
            if (decode_counter(es, e, &r, &idx)) {
                d[k] = es.base[r] + es.dst[r][idx];   // 4 independent loads
                ok[k] = true;
            }
        }
    }
#pragma unroll
    for (int k = 0; k < 4; k++)
        if (ok[k]) atomicAdd(&g_cnt[d[k]], 1);
}

__global__ __launch_bounds__(256)
void scan1() {
    __shared__ int sh[256];
    int t    = threadIdx.x;
    int base = blockIdx.x * 1024 + t * 4;
    int v[4];
#pragma unroll
    for (int j = 0; j < 4; j++)
        v[j] = (base + j < NDEG) ? g_cnt[base + j] : 0;
    int tsum = v[0] + v[1] + v[2] + v[3];
    sh[t] = tsum;
    __syncthreads();
    for (int d = 1; d < 256; d <<= 1) {
        int x = (t >= d) ? sh[t - d] : 0;
        __syncthreads();
        sh[t] += x;
        __syncthreads();
    }
    int run = sh[t] - tsum;
#pragma unroll
    for (int j = 0; j < 4; j++) {
        if (base + j < NDEG) g_off[base + j] = run;
        run += v[j];
    }
    if (t == 255) g_bsum[blockIdx.x] = sh[255];
}

__global__ __launch_bounds__(256)
void scan2() {
    __shared__ int sh[256];
    int t = threadIdx.x;
    int v = (t < NSCAN) ? g_bsum[t] : 0;
    sh[t] = v;
    __syncthreads();
    for (int d = 1; d < 256; d <<= 1) {
        int x = (t >= d) ? sh[t - d] : 0;
        __syncthreads();
        sh[t] += x;
        __syncthreads();
    }
    g_boff[t] = sh[t] - v;
}

__global__ __launch_bounds__(256)
void scan3() {
    int i = blockIdx.x * blockDim.x + threadIdx.x;
    if (i < NDEG) g_off[i] += g_boff[i >> 10];
}

__global__ __launch_bounds__(256)
void permute_all(ES es, int total, int stride) {
    int t = blockIdx.x * blockDim.x + threadIdx.x;
    if (t >= stride) return;              // <- duplication guard
    int dc[4];                       // counter index
    unsigned long long pk[4];        // packed payload
    bool ok[4];
#pragma unroll
    for (int k = 0; k < 4; k++) {
        int e = t + k * stride;
        ok[k] = false;
        if (e < total) {
            int r, idx;
            if (decode_counter(es, e, &r, &idx)) {
                int   s = es.src[r][idx];            // independent loads
                int   d = es.dst[r][idx];
                float w = es.w[r][idx];
                dc[k] = es.base[r] + d;
                pk[k] = (unsigned long long)(unsigned)s |
                        ((unsigned long long)__float_as_uint(w) << 32);
                ok[k] = true;
            }
        }
    }
#pragma unroll
    for (int k = 0; k < 4; k++) {
        if (ok[k]) {
            int pos = g_off[dc[k]] + atomicAdd(&g_cur[dc[k]], 1);
            g_edge[pos] = pk[k];
        }
    }
}

// ---------------------------------------------------------------------------
// Split-BF16 tensor-core GEMM + bias: C[M x 128] = A[M x DIN] @ W[DIN x 128]+b
// mma.sync.m16n8k16.bf16 with 2-term split + 3-product compensation:
//   a = a_hi + a_lo (both bf16);  d += a_hi*b_hi + a_lo*b_hi + a_hi*b_lo
// -> O(2^-16) relative error; fp32 accumulate.
// BM=128, BN=128, BK=16, 256 threads = 8 warps (4 along M x 2 along N).
// Smem row stride 12 u32 (8 used + 4 pad): conflict-free fragment LDS.
// blockIdx.y selects one of three (W, b, C) sets.
// ---------------------------------------------------------------------------
__device__ __forceinline__ void split_pack(float x0, float x1,
                                           uint32_t& hi, uint32_t& lo) {
    __nv_bfloat16 h0 = __float2bfloat16(x0);
    __nv_bfloat16 h1 = __float2bfloat16(x1);
    __nv_bfloat16 l0 = __float2bfloat16(x0 - __bfloat162float(h0));
    __nv_bfloat16 l1 = __float2bfloat16(x1 - __bfloat162float(h1));
    hi = (uint32_t)__bfloat16_as_ushort(h0) |
         ((uint32_t)__bfloat16_as_ushort(h1) << 16);
    lo = (uint32_t)__bfloat16_as_ushort(l0) |
         ((uint32_t)__bfloat16_as_ushort(l1) << 16);
}

__device__ __forceinline__ void mma_bf16(float* d, const uint32_t* a,
                                         const uint32_t* b) {
    asm volatile(
        "mma.sync.aligned.m16n8k16.row.col.f32.bf16.bf16.f32 "
        "{%0,%1,%2,%3}, {%4,%5,%6,%7}, {%8,%9}, {%0,%1,%2,%3};"
        : "+f"(d[0]), "+f"(d[1]), "+f"(d[2]), "+f"(d[3])
        : "r"(a[0]), "r"(a[1]), "r"(a[2]), "r"(a[3]), "r"(b[0]), "r"(b[1]));
}

template <int DIN>
__global__ __launch_bounds__(256)
void gemm_bf16(const float* __restrict__ A,
               const float* __restrict__ W0, const float* __restrict__ b0,
               float* __restrict__ C0,
               const float* __restrict__ W1, const float* __restrict__ b1,
               float* __restrict__ C1,
               const float* __restrict__ W2, const float* __restrict__ b2,
               float* __restrict__ C2, int M) {
    constexpr int S = 12;   // u32 row stride (8 kp used + 4 pad)
    __shared__ uint32_t As_hi[128 * S], As_lo[128 * S];   // [row][kp]
    __shared__ uint32_t Bs_hi[128 * S], Bs_lo[128 * S];   // [n][kp]

    const float* W    = (blockIdx.y == 0) ? W0 : (blockIdx.y == 1) ? W1 : W2;
    const float* bias = (blockIdx.y == 0) ? b0 : (blockIdx.y == 1) ? b1 : b2;
    float*       C    = (blockIdx.y == 0) ? C0 : (blockIdx.y == 1) ? C1 : C2;

    const int t    = threadIdx.x;
    const int m0   = blockIdx.x * 128;
    const int wid  = t >> 5;
    const int lane = t & 31;
    const int g    = lane >> 2;   // group id  (0..7)
    const int tg   = lane & 3;    // thread-in-group (0..3)
    const int m0w  = (wid & 3) * 32;   // warp M origin
    const int n0w  = (wid >> 2) * 64;  // warp N origin

    const int fr  = t >> 1;          // fill row (A) / col n (B): 0..127
    const int fk8 = (t & 1) * 8;     // k offset 0 or 8
    const int fkp = fk8 >> 1;        // kp offset 0 or 4

    float acc[2][8][4];
#pragma unroll
    for (int mt = 0; mt < 2; mt++)
#pragma unroll
        for (int nt = 0; nt < 8; nt++)
#pragma unroll
            for (int j = 0; j < 4; j++) acc[mt][nt][j] = 0.0f;

    for (int k0 = 0; k0 < DIN; k0 += 16) {
        // ---- A fill: row fr, k = k0+fk8 .. +7, split+pack into 4 u32. ----
        {
            float v[8];
            if (m0 + fr < M) {
                const float* src = A + (size_t)(m0 + fr) * DIN + k0 + fk8;
                *(float4*)(v)     = *(const float4*)(src);
                *(float4*)(v + 4) = *(const float4*)(src + 4);
            } else {
#pragma unroll
                for (int j = 0; j < 8; j++) v[j] = 0.0f;
            }
#pragma unroll
            for (int j = 0; j < 4; j++) {
                uint32_t hi, lo;
                split_pack(v[2 * j], v[2 * j + 1], hi, lo);
                As_hi[fr * S + fkp + j] = hi;
                As_lo[fr * S + fkp + j] = lo;
            }
        }
        // ---- B fill: col n = fr, k = k0+fk8 .. +7 (8 strided scalars). ----
        {
            float v[8];
#pragma unroll
            for (int j = 0; j < 8; j++)
                v[j] = W[(size_t)(k0 + fk8 + j) * DO + fr];
#pragma unroll
            for (int j = 0; j < 4; j++) {
                uint32_t hi, lo;
                split_pack(v[2 * j], v[2 * j + 1], hi, lo);
                Bs_hi[fr * S + fkp + j] = hi;
                Bs_lo[fr * S + fkp + j] = lo;
            }
        }
        __syncthreads();

        // ---- One m16n8k16 step covers the whole 16-wide k tile. ----
        uint32_t a_hi[2][4], a_lo[2][4];
#pragma unroll
        for (int mt = 0; mt < 2; mt++) {
            int r0 = (m0w + mt * 16 + g) * S;
            int r1 = (m0w + mt * 16 + g + 8) * S;
            a_hi[mt][0] = As_hi[r0 + tg];
            a_hi[mt][1] = As_hi[r1 + tg];
            a_hi[mt][2] = As_hi[r0 + tg + 4];
            a_hi[mt][3] = As_hi[r1 + tg + 4];
            a_lo[mt][0] = As_lo[r0 + tg];
            a_lo[mt][1] = As_lo[r1 + tg];
            a_lo[mt][2] = As_lo[r0 + tg + 4];
            a_lo[mt][3] = As_lo[r1 + tg + 4];
        }
#pragma unroll
        for (int nt = 0; nt < 8; nt++) {
            int nb = (n0w + nt * 8 + g) * S;
            uint32_t b_hi[2], b_lo[2];
            b_hi[0] = Bs_hi[nb + tg];
            b_hi[1] = Bs_hi[nb + tg + 4];
            b_lo[0] = Bs_lo[nb + tg];
            b_lo[1] = Bs_lo[nb + tg + 4];
#pragma unroll
            for (int mt = 0; mt < 2; mt++) {
                mma_bf16(acc[mt][nt], a_hi[mt], b_hi);
                mma_bf16(acc[mt][nt], a_lo[mt], b_hi);
                mma_bf16(acc[mt][nt], a_hi[mt], b_lo);
            }
        }
        __syncthreads();
    }

    // Epilogue: bias + store.
#pragma unroll
    for (int nt = 0; nt < 8; nt++) {
        int col = n0w + nt * 8 + 2 * tg;
        float bx = bias[col];
        float by = bias[col + 1];
#pragma unroll
        for (int mt = 0; mt < 2; mt++) {
            int mr = m0 + m0w + mt * 16 + g;
            if (mr < M) {
                float2 o = make_float2(acc[mt][nt][0] + bx,
                                       acc[mt][nt][1] + by);
                *(float2*)(C + (size_t)mr * DO + col) = o;
            }
            if (mr + 8 < M) {
                float2 o = make_float2(acc[mt][nt][2] + bx,
                                       acc[mt][nt][3] + by);
                *(float2*)(C + (size_t)(mr + 8) * DO + col) = o;
            }
        }
    }
}

// ---------------------------------------------------------------------------
// Aggregation (CSR, atomic-free): ONE WARP per dst row, lane owns a float4
// column slice -> one LDG.128 per lane per edge. 2x-unrolled edge loop.
// Mean + cross-etype sum + coalesced float4 output store fused.
// ---------------------------------------------------------------------------
__device__ __forceinline__ float4 mean_row_w(const float* __restrict__ Wh,
                                             int cnt_base, int row, int lane) {
    int beg = g_off[cnt_base + row];
    int deg = g_cnt[cnt_base + row];
    float4 a0 = make_float4(0.f, 0.f, 0.f, 0.f);
    float4 a1 = make_float4(0.f, 0.f, 0.f, 0.f);
    int e = 0;
    for (; e + 2 <= deg; e += 2) {
        unsigned long long pA = g_edge[beg + e];
        unsigned long long pB = g_edge[beg + e + 1];
        int   sA = (int)(unsigned)pA;
        int   sB = (int)(unsigned)pB;
        float wA = __uint_as_float((unsigned)(pA >> 32));
        float wB = __uint_as_float((unsigned)(pB >> 32));
        float4 vA = *(const float4*)(Wh + (size_t)sA * DO + lane * 4);
        float4 vB = *(const float4*)(Wh + (size_t)sB * DO + lane * 4);
        a0.x += wA * vA.x; a0.y += wA * vA.y;
        a0.z += wA * vA.z; a0.w += wA * vA.w;
        a1.x += wB * vB.x; a1.y += wB * vB.y;
        a1.z += wB * vB.z; a1.w += wB * vB.w;
    }
    if (e < deg) {
        unsigned long long p = g_edge[beg + e];
        int   s = (int)(unsigned)p;
        float w = __uint_as_float((unsigned)(p >> 32));
        float4 v = *(const float4*)(Wh + (size_t)s * DO + lane * 4);
        a0.x += w * v.x; a0.y += w * v.y;
        a0.z += w * v.z; a0.w += w * v.w;
    }
    float inv = (deg > 0) ? 1.0f / (float)deg : 0.0f;
    return make_float4((a0.x + a1.x) * inv, (a0.y + a1.y) * inv,
                       (a0.z + a1.z) * inv, (a0.w + a1.w) * inv);
}

__global__ __launch_bounds__(256)
void agg1(const float* __restrict__ Wh, int cnt_base, int out_row0,
          float* __restrict__ out, int nrows) {
    int row  = blockIdx.x * 8 + (threadIdx.x >> 5);
    int lane = threadIdx.x & 31;
    if (row >= nrows) return;
    float4 r = mean_row_w(Wh, cnt_base, row, lane);
    *(float4*)(out + (size_t)(out_row0 + row) * DO + lane * 4) = r;
}

__global__ __launch_bounds__(256)
void agg2(const float* __restrict__ WhA, int baseA,
          const float* __restrict__ WhB, int baseB, int out_row0,
          float* __restrict__ out, int nrows) {
    int row  = blockIdx.x * 8 + (threadIdx.x >> 5);
    int lane = threadIdx.x & 31;
    if (row >= nrows) return;
    float4 rA = mean_row_w(WhA, baseA, row, lane);
    float4 rB = mean_row_w(WhB, baseB, row, lane);
    float4 o  = make_float4(rA.x + rB.x, rA.y + rB.y,
                            rA.z + rB.z, rA.w + rB.w);
    *(float4*)(out + (size_t)(out_row0 + row) * DO + lane * 4) = o;
}

// ---------------------------------------------------------------------------
// Host entry.
// Input order (metadata): 0 feat_word, 1 feat_topic,
//   2-4 ww(src,dst,w), 5-7 wt, 8-10 wd, 11-13 td, 14-16 tt,
//   17/18 W_ww/b_ww, 19/20 W_wt/b_wt, 21/22 W_wd/b_wd, 23/24 W_td/b_td,
//   25/26 W_tt/b_tt
//
// DAG (capture-legal fork), R13 topology. Issuance ORDER puts G_words as the
// 6th kernel launch so ncu's "-s 5 -c 1" lands on it (DAG unchanged:
// permute_all still follows scan3 in-stream on s2).
//   legacy: evFork -> G_words(y=3, evGw) -> G_topics(y=2, evGt)
//           -> [evCSR] agg_doc -> [evS2] join
//   s2:     [evFork] zero_cnt -> hist_all -> scan x3 -> permute_all (evCSR)
//           -> [evGw] agg_word -> [evGt] agg_topic (evS2)
// ---------------------------------------------------------------------------
extern "C" void kernel_launch(void* const* d_in, const int* in_sizes, int n_in,
                              void* d_out, int out_size) {
    static cudaStream_t s2 = nullptr;
    static cudaEvent_t  evFork, evCSR, evGw, evGt, evS2;
    if (s2 == nullptr) {
        cudaStreamCreateWithFlags(&s2, cudaStreamNonBlocking);
        cudaEventCreateWithFlags(&evFork, cudaEventDisableTiming);
        cudaEventCreateWithFlags(&evCSR,  cudaEventDisableTiming);
        cudaEventCreateWithFlags(&evGw,   cudaEventDisableTiming);
        cudaEventCreateWithFlags(&evGt,   cudaEventDisableTiming);
        cudaEventCreateWithFlags(&evS2,   cudaEventDisableTiming);
    }

    const float* feat_word  = (const float*)d_in[0];
    const float* feat_topic = (const float*)d_in[1];

    // Edge sets in CSR order: ww, wt, tt, wd, td.
    ES es;
    es.src[0] = (const int*)d_in[2];  es.dst[0] = (const int*)d_in[3];
    es.w[0] = (const float*)d_in[4];  es.E[0] = in_sizes[2];  es.base[0] = DEG_WW;
    es.src[1] = (const int*)d_in[5];  es.dst[1] = (const int*)d_in[6];
    es.w[1] = (const float*)d_in[7];  es.E[1] = in_sizes[5];  es.base[1] = DEG_WT;
    es.src[2] = (const int*)d_in[14]; es.dst[2] = (const int*)d_in[15];
    es.w[2] = (const float*)d_in[16]; es.E[2] = in_sizes[14]; es.base[2] = DEG_TT;
    es.src[3] = (const int*)d_in[8];  es.dst[3] = (const int*)d_in[9];
    es.w[3] = (const float*)d_in[10]; es.E[3] = in_sizes[8];  es.base[3] = DEG_WD;
    es.src[4] = (const int*)d_in[11]; es.dst[4] = (const int*)d_in[12];
    es.w[4] = (const float*)d_in[13]; es.E[4] = in_sizes[11]; es.base[4] = DEG_TD;
    int totalE = es.E[0] + es.E[1] + es.E[2] + es.E[3] + es.E[4];
    int strideE = (totalE + 3) / 4;   // 4 edges per thread

    const float* W_ww = (const float*)d_in[17]; const float* b_ww = (const float*)d_in[18];
    const float* W_wt = (const float*)d_in[19]; const float* b_wt = (const float*)d_in[20];
    const float* W_wd = (const float*)d_in[21]; const float* b_wd = (const float*)d_in[22];
    const float* W_td = (const float*)d_in[23]; const float* b_td = (const float*)d_in[24];
    const float* W_tt = (const float*)d_in[25]; const float* b_tt = (const float*)d_in[26];

    float* out = (float*)d_out;

    float* p_ww; cudaGetSymbolAddress((void**)&p_ww, g_Wh_ww);
    float* p_wt; cudaGetSymbolAddress((void**)&p_wt, g_Wh_wt);
    float* p_wd; cudaGetSymbolAddress((void**)&p_wd, g_Wh_wd);
    float* p_td; cudaGetSymbolAddress((void**)&p_td, g_Wh_td);
    float* p_tt; cudaGetSymbolAddress((void**)&p_tt, g_Wh_tt);

    // ---- Fork s2 from the capture (legacy) stream. ----
    cudaEventRecord(evFork, 0);
    cudaStreamWaitEvent(s2, evFork, 0);

    // ---- s2: CSR front half (launches 1-5). ----
    zero_cnt<<<(NDEG + 255) / 256, 256, 0, s2>>>();
    hist_all<<<(strideE + 255) / 256, 256, 0, s2>>>(es, totalE, strideE);
    scan1<<<NSCAN, 256, 0, s2>>>();
    scan2<<<1, 256, 0, s2>>>();
    scan3<<<(NDEG + 255) / 256, 256, 0, s2>>>();

    // ---- legacy: word projections (launch #6 -> ncu -s 5 lands here). ----
    {
        int gw = (NW + 127) / 128;   // 391 -> y=3: 1173 CTAs
        gemm_bf16<DW><<<dim3(gw, 3), 256>>>(feat_word,
                                            W_ww, b_ww, p_ww,
                                            W_wt, b_wt, p_wt,
                                            W_wd, b_wd, p_wd, NW);
        cudaEventRecord(evGw, 0);
    }

    // ---- s2: CSR back half. ----
    permute_all<<<(strideE + 255) / 256, 256, 0, s2>>>(es, totalE, strideE);
    cudaEventRecord(evCSR, s2);

    // ---- legacy: topic projections. ----
    {
        int gt = (NT + 127) / 128;   // 16
        gemm_bf16<128><<<dim3(gt, 2), 256>>>(feat_topic,
                                             W_tt, b_tt, p_tt,
                                             W_td, b_td, p_td,
                                             W_td, b_td, p_td, NT);
        cudaEventRecord(evGt, 0);
    }

    // ---- s2: aggregates as dependencies resolve (CSR is in-stream). ----
    cudaStreamWaitEvent(s2, evGw, 0);
    agg1<<<(NW + 7) / 8, 256, 0, s2>>>(p_ww, DEG_WW, 0, out, NW);
    cudaStreamWaitEvent(s2, evGt, 0);
    agg2<<<(NT + 7) / 8, 256, 0, s2>>>(p_wt, DEG_WT, p_tt, DEG_TT, NW, out, NT);
    cudaEventRecord(evS2, s2);

    // ---- legacy: doc aggregate (GEMMs in-stream; CSR via event). ----
    cudaStreamWaitEvent(0, evCSR, 0);
    agg2<<<(ND + 7) / 8, 256>>>(p_wd, DEG_WD, p_td, DEG_TD, NW + NT, out, ND);

    // ---- join. ----
    cudaStreamWaitEvent(0, evS2, 0);
}

// round 17
// speedup vs baseline: 1.1181x; 1.0171x over previous
#include <cuda_runtime.h>
#include <cuda_bf16.h>
#include <cstdint>

// Problem dimensions (fixed by the reference).
#define NW 50000
#define NT 2000
#define ND 50000
#define DO 128
#define DW 256
#define E_MAX 2200000   // total edges = 2.1M; padded

// Concatenated per-(relation,dst) counter layout.
constexpr int DEG_WW = 0;
constexpr int DEG_WT = NW;
constexpr int DEG_TT = NW + NT;
constexpr int DEG_WD = NW + 2 * NT;
constexpr int DEG_TD = NW + 2 * NT + ND;
constexpr int NDEG   = NW + 2 * NT + 2 * ND;   // 154000
constexpr int NSCAN  = (NDEG + 1023) / 1024;   // 151 scan blocks
constexpr int NROWS  = NW + NT + ND;           // 102000 output rows

// ---------------------------------------------------------------------------
// Scratch (static __device__ arrays — allocation-free per harness rules).
// ---------------------------------------------------------------------------
__device__ float g_Wh_ww[(size_t)NW * DO];
__device__ float g_Wh_wt[(size_t)NW * DO];
__device__ float g_Wh_wd[(size_t)NW * DO];
__device__ float g_Wh_td[(size_t)NT * DO];
__device__ float g_Wh_tt[(size_t)NT * DO];

__device__ int      g_cnt[NDEG];    // per-(rel,dst) degree
__device__ int      g_cur[NDEG];    // fill cursors for permute
__device__ int      g_off[NDEG];    // exclusive scan of g_cnt (global)
__device__ int      g_bsum[256];    // scan block sums
__device__ int      g_boff[256];    // scanned block sums

__device__ unsigned long long g_edge[E_MAX];  // packed (src | w<<32), dst-grouped

// Edge-set bundle for merged CSR kernels (passed by value).
struct ES {
    const int*   src[5];
    const int*   dst[5];
    const float* w[5];
    int          E[5];
    int          base[5];
};

// ---------------------------------------------------------------------------
// CSR build. hist/permute are 4-edge-per-thread batched: the 4 index loads
// are issued independently BEFORE any atomic (MLP=4). Guard t < stride
// prevents round-up threads from duplicating edges.
// ---------------------------------------------------------------------------
__global__ void zero_cnt() {
    int i = blockIdx.x * blockDim.x + threadIdx.x;
    if (i < NDEG) { g_cnt[i] = 0; g_cur[i] = 0; }
}

__device__ __forceinline__ int decode_counter(const ES& es, int e, int* rel,
                                              int* idx) {
#pragma unroll
    for (int r = 0; r < 5; r++) {
        if (e < es.E[r]) { *rel = r; *idx = e; return 1; }
        e -= es.E[r];
    }
    return 0;
}

__global__ __launch_bounds__(256)
void hist_all(ES es, int total, int stride) {
    int t = blockIdx.x * blockDim.x + threadIdx.x;
    if (t >= stride) return;              // duplication guard
    int d[4]; bool ok[4];
#pragma unroll
    for (int k = 0; k < 4; k++) {
        int e = t + k * stride;
        ok[k] = false;
        if (e < total) {
            int r, idx;
            if (decode_counter(es, e, &r, &idx)) {
                d[k] = es.base[r] + es.dst[r][idx];   // 4 independent loads
                ok[k] = true;
            }
        }
    }
#pragma unroll
    for (int k = 0; k < 4; k++)
        if (ok[k]) atomicAdd(&g_cnt[d[k]], 1);
}

__global__ __launch_bounds__(256)
void scan1() {
    __shared__ int sh[256];
    int t    = threadIdx.x;
    int base = blockIdx.x * 1024 + t * 4;
    int v[4];
#pragma unroll
    for (int j = 0; j < 4; j++)
        v[j] = (base + j < NDEG) ? g_cnt[base + j] : 0;
    int tsum = v[0] + v[1] + v[2] + v[3];
    sh[t] = tsum;
    __syncthreads();
    for (int d = 1; d < 256; d <<= 1) {
        int x = (t >= d) ? sh[t - d] : 0;
        __syncthreads();
        sh[t] += x;
        __syncthreads();
    }
    int run = sh[t] - tsum;
#pragma unroll
    for (int j = 0; j < 4; j++) {
        if (base + j < NDEG) g_off[base + j] = run;
        run += v[j];
    }
    if (t == 255) g_bsum[blockIdx.x] = sh[255];
}

__global__ __launch_bounds__(256)
void scan2() {
    __shared__ int sh[256];
    int t = threadIdx.x;
    int v = (t < NSCAN) ? g_bsum[t] : 0;
    sh[t] = v;
    __syncthreads();
    for (int d = 1; d < 256; d <<= 1) {
        int x = (t >= d) ? sh[t - d] : 0;
        __syncthreads();
        sh[t] += x;
        __syncthreads();
    }
    g_boff[t] = sh[t] - v;
}

__global__ __launch_bounds__(256)
void scan3() {
    int i = blockIdx.x * blockDim.x + threadIdx.x;
    if (i < NDEG) g_off[i] += g_boff[i >> 10];
}

__global__ __launch_bounds__(256)
void permute_all(ES es, int total, int stride) {
    int t = blockIdx.x * blockDim.x + threadIdx.x;
    if (t >= stride) return;              // duplication guard
    int dc[4];
    unsigned long long pk[4];
    bool ok[4];
#pragma unroll
    for (int k = 0; k < 4; k++) {
        int e = t + k * stride;
        ok[k] = false;
        if (e < total) {
            int r, idx;
            if (decode_counter(es, e, &r, &idx)) {
                int   s = es.src[r][idx];
                int   d = es.dst[r][idx];
                float w = es.w[r][idx];
                dc[k] = es.base[r] + d;
                pk[k] = (unsigned long long)(unsigned)s |
                        ((unsigned long long)__float_as_uint(w) << 32);
                ok[k] = true;
            }
        }
    }
#pragma unroll
    for (int k = 0; k < 4; k++) {
        if (ok[k]) {
            int pos = g_off[dc[k]] + atomicAdd(&g_cur[dc[k]], 1);
            g_edge[pos] = pk[k];
        }
    }
}

// ---------------------------------------------------------------------------
// Split-BF16 tensor-core GEMM + bias: C[M x 128] = A[M x DIN] @ W[DIN x 128]+b
// mma.sync.m16n8k16.bf16 with 2-term split + 3-product compensation:
//   a = a_hi + a_lo (both bf16);  d += a_hi*b_hi + a_lo*b_hi + a_hi*b_lo
// -> O(2^-16) relative error; fp32 accumulate.
// BM=128, BN=128, BK=16, 256 threads = 8 warps (4 along M x 2 along N).
// Smem row stride 12 u32 (8 used + 4 pad): conflict-free fragment LDS.
// blockIdx.y selects one of three (W, b, C) sets.
// ---------------------------------------------------------------------------
__device__ __forceinline__ void split_pack(float x0, float x1,
                                           uint32_t& hi, uint32_t& lo) {
    __nv_bfloat16 h0 = __float2bfloat16(x0);
    __nv_bfloat16 h1 = __float2bfloat16(x1);
    __nv_bfloat16 l0 = __float2bfloat16(x0 - __bfloat162float(h0));
    __nv_bfloat16 l1 = __float2bfloat16(x1 - __bfloat162float(h1));
    hi = (uint32_t)__bfloat16_as_ushort(h0) |
         ((uint32_t)__bfloat16_as_ushort(h1) << 16);
    lo = (uint32_t)__bfloat16_as_ushort(l0) |
         ((uint32_t)__bfloat16_as_ushort(l1) << 16);
}

__device__ __forceinline__ void mma_bf16(float* d, const uint32_t* a,
                                         const uint32_t* b) {
    asm volatile(
        "mma.sync.aligned.m16n8k16.row.col.f32.bf16.bf16.f32 "
        "{%0,%1,%2,%3}, {%4,%5,%6,%7}, {%8,%9}, {%0,%1,%2,%3};"
        : "+f"(d[0]), "+f"(d[1]), "+f"(d[2]), "+f"(d[3])
        : "r"(a[0]), "r"(a[1]), "r"(a[2]), "r"(a[3]), "r"(b[0]), "r"(b[1]));
}

template <int DIN>
__global__ __launch_bounds__(256)
void gemm_bf16(const float* __restrict__ A,
               const float* __restrict__ W0, const float* __restrict__ b0,
               float* __restrict__ C0,
               const float* __restrict__ W1, const float* __restrict__ b1,
               float* __restrict__ C1,
               const float* __restrict__ W2, const float* __restrict__ b2,
               float* __restrict__ C2, int M) {
    constexpr int S = 12;   // u32 row stride (8 kp used + 4 pad)
    __shared__ uint32_t As_hi[128 * S], As_lo[128 * S];   // [row][kp]
    __shared__ uint32_t Bs_hi[128 * S], Bs_lo[128 * S];   // [n][kp]

    const float* W    = (blockIdx.y == 0) ? W0 : (blockIdx.y == 1) ? W1 : W2;
    const float* bias = (blockIdx.y == 0) ? b0 : (blockIdx.y == 1) ? b1 : b2;
    float*       C    = (blockIdx.y == 0) ? C0 : (blockIdx.y == 1) ? C1 : C2;

    const int t    = threadIdx.x;
    const int m0   = blockIdx.x * 128;
    const int wid  = t >> 5;
    const int lane = t & 31;
    const int g    = lane >> 2;   // group id  (0..7)
    const int tg   = lane & 3;    // thread-in-group (0..3)
    const int m0w  = (wid & 3) * 32;   // warp M origin
    const int n0w  = (wid >> 2) * 64;  // warp N origin

    const int fr  = t >> 1;          // fill row (A) / col n (B): 0..127
    const int fk8 = (t & 1) * 8;     // k offset 0 or 8
    const int fkp = fk8 >> 1;        // kp offset 0 or 4

    float acc[2][8][4];
#pragma unroll
    for (int mt = 0; mt < 2; mt++)
#pragma unroll
        for (int nt = 0; nt < 8; nt++)
#pragma unroll
            for (int j = 0; j < 4; j++) acc[mt][nt][j] = 0.0f;

    for (int k0 = 0; k0 < DIN; k0 += 16) {
        // ---- A fill: row fr, k = k0+fk8 .. +7, split+pack into 4 u32. ----
        {
            float v[8];
            if (m0 + fr < M) {
                const float* src = A + (size_t)(m0 + fr) * DIN + k0 + fk8;
                *(float4*)(v)     = *(const float4*)(src);
                *(float4*)(v + 4) = *(const float4*)(src + 4);
            } else {
#pragma unroll
                for (int j = 0; j < 8; j++) v[j] = 0.0f;
            }
#pragma unroll
            for (int j = 0; j < 4; j++) {
                uint32_t hi, lo;
                split_pack(v[2 * j], v[2 * j + 1], hi, lo);
                As_hi[fr * S + fkp + j] = hi;
                As_lo[fr * S + fkp + j] = lo;
            }
        }
        // ---- B fill: col n = fr, k = k0+fk8 .. +7 (8 strided scalars). ----
        {
            float v[8];
#pragma unroll
            for (int j = 0; j < 8; j++)
                v[j] = W[(size_t)(k0 + fk8 + j) * DO + fr];
#pragma unroll
            for (int j = 0; j < 4; j++) {
                uint32_t hi, lo;
                split_pack(v[2 * j], v[2 * j + 1], hi, lo);
                Bs_hi[fr * S + fkp + j] = hi;
                Bs_lo[fr * S + fkp + j] = lo;
            }
        }
        __syncthreads();

        // ---- One m16n8k16 step covers the whole 16-wide k tile. ----
        uint32_t a_hi[2][4], a_lo[2][4];
#pragma unroll
        for (int mt = 0; mt < 2; mt++) {
            int r0 = (m0w + mt * 16 + g) * S;
            int r1 = (m0w + mt * 16 + g + 8) * S;
            a_hi[mt][0] = As_hi[r0 + tg];
            a_hi[mt][1] = As_hi[r1 + tg];
            a_hi[mt][2] = As_hi[r0 + tg + 4];
            a_hi[mt][3] = As_hi[r1 + tg + 4];
            a_lo[mt][0] = As_lo[r0 + tg];
            a_lo[mt][1] = As_lo[r1 + tg];
            a_lo[mt][2] = As_lo[r0 + tg + 4];
            a_lo[mt][3] = As_lo[r1 + tg + 4];
        }
#pragma unroll
        for (int nt = 0; nt < 8; nt++) {
            int nb = (n0w + nt * 8 + g) * S;
            uint32_t b_hi[2], b_lo[2];
            b_hi[0] = Bs_hi[nb + tg];
            b_hi[1] = Bs_hi[nb + tg + 4];
            b_lo[0] = Bs_lo[nb + tg];
            b_lo[1] = Bs_lo[nb + tg + 4];
#pragma unroll
            for (int mt = 0; mt < 2; mt++) {
                mma_bf16(acc[mt][nt], a_hi[mt], b_hi);
                mma_bf16(acc[mt][nt], a_lo[mt], b_hi);
                mma_bf16(acc[mt][nt], a_hi[mt], b_lo);
            }
        }
        __syncthreads();
    }

    // Epilogue: bias + store.
#pragma unroll
    for (int nt = 0; nt < 8; nt++) {
        int col = n0w + nt * 8 + 2 * tg;
        float bx = bias[col];
        float by = bias[col + 1];
#pragma unroll
        for (int mt = 0; mt < 2; mt++) {
            int mr = m0 + m0w + mt * 16 + g;
            if (mr < M) {
                float2 o = make_float2(acc[mt][nt][0] + bx,
                                       acc[mt][nt][1] + by);
                *(float2*)(C + (size_t)mr * DO + col) = o;
            }
            if (mr + 8 < M) {
                float2 o = make_float2(acc[mt][nt][2] + bx,
                                       acc[mt][nt][3] + by);
                *(float2*)(C + (size_t)(mr + 8) * DO + col) = o;
            }
        }
    }
}

// ---------------------------------------------------------------------------
// FUSED aggregation (CSR, atomic-free): ONE kernel covers ALL 102000 output
// rows (word | topic | doc). One warp per dst row, lane owns a float4 column
// slice -> one LDG.128 per lane per edge. 2x-unrolled edge loop. Mean +
// cross-etype sum + coalesced float4 output store fused. Full-chip wave
// packing across all rows; single launch replaces 3.
// ---------------------------------------------------------------------------
__device__ __forceinline__ float4 mean_row_w(const float* __restrict__ Wh,
                                             int cnt_base, int row, int lane) {
    int beg = g_off[cnt_base + row];
    int deg = g_cnt[cnt_base + row];
    float4 a0 = make_float4(0.f, 0.f, 0.f, 0.f);
    float4 a1 = make_float4(0.f, 0.f, 0.f, 0.f);
    int e = 0;
    for (; e + 2 <= deg; e += 2) {
        unsigned long long pA = g_edge[beg + e];
        unsigned long long pB = g_edge[beg + e + 1];
        int   sA = (int)(unsigned)pA;
        int   sB = (int)(unsigned)pB;
        float wA = __uint_as_float((unsigned)(pA >> 32));
        float wB = __uint_as_float((unsigned)(pB >> 32));
        float4 vA = *(const float4*)(Wh + (size_t)sA * DO + lane * 4);
        float4 vB = *(const float4*)(Wh + (size_t)sB * DO + lane * 4);
        a0.x += wA * vA.x; a0.y += wA * vA.y;
        a0.z += wA * vA.z; a0.w += wA * vA.w;
        a1.x += wB * vB.x; a1.y += wB * vB.y;
        a1.z += wB * vB.z; a1.w += wB * vB.w;
    }
    if (e < deg) {
        unsigned long long p = g_edge[beg + e];
        int   s = (int)(unsigned)p;
        float w = __uint_as_float((unsigned)(p >> 32));
        float4 v = *(const float4*)(Wh + (size_t)s * DO + lane * 4);
        a0.x += w * v.x; a0.y += w * v.y;
        a0.z += w * v.z; a0.w += w * v.w;
    }
    float inv = (deg > 0) ? 1.0f / (float)deg : 0.0f;
    return make_float4((a0.x + a1.x) * inv, (a0.y + a1.y) * inv,
                       (a0.z + a1.z) * inv, (a0.w + a1.w) * inv);
}

__global__ __launch_bounds__(256)
void agg_all(const float* __restrict__ Wh_ww, const float* __restrict__ Wh_wt,
             const float* __restrict__ Wh_tt, const float* __restrict__ Wh_wd,
             const float* __restrict__ Wh_td, float* __restrict__ out) {
    int row  = blockIdx.x * 8 + (threadIdx.x >> 5);
    int lane = threadIdx.x & 31;
    if (row >= NROWS) return;

    float4 o;
    if (row < NW) {
        o = mean_row_w(Wh_ww, DEG_WW, row, lane);
    } else if (row < NW + NT) {
        int r = row - NW;
        float4 a = mean_row_w(Wh_wt, DEG_WT, r, lane);
        float4 b = mean_row_w(Wh_tt, DEG_TT, r, lane);
        o = make_float4(a.x + b.x, a.y + b.y, a.z + b.z, a.w + b.w);
    } else {
        int r = row - NW - NT;
        float4 a = mean_row_w(Wh_wd, DEG_WD, r, lane);
        float4 b = mean_row_w(Wh_td, DEG_TD, r, lane);
        o = make_float4(a.x + b.x, a.y + b.y, a.z + b.z, a.w + b.w);
    }
    *(float4*)(out + (size_t)row * DO + lane * 4) = o;
}

// ---------------------------------------------------------------------------
// Host entry.
// Input order (metadata): 0 feat_word, 1 feat_topic,
//   2-4 ww(src,dst,w), 5-7 wt, 8-10 wd, 11-13 td, 14-16 tt,
//   17/18 W_ww/b_ww, 19/20 W_wt/b_wt, 21/22 W_wd/b_wd, 23/24 W_td/b_td,
//   25/26 W_tt/b_tt
//
// DAG (capture-legal fork):
//   legacy: evFork -> G_words(y=3) -> [evS2] agg_all -> done
//   s2:     [evFork] zero_cnt -> hist_all -> scan x3 -> permute_all
//           -> G_topics(y=2)   (runs CONCURRENT with G_words!)  -> evS2
// Critical path = max(G_words, CSR + G_topics) + agg_all. 9 launches.
// ---------------------------------------------------------------------------
extern "C" void kernel_launch(void* const* d_in, const int* in_sizes, int n_in,
                              void* d_out, int out_size) {
    static cudaStream_t s2 = nullptr;
    static cudaEvent_t  evFork, evS2;
    if (s2 == nullptr) {
        cudaStreamCreateWithFlags(&s2, cudaStreamNonBlocking);
        cudaEventCreateWithFlags(&evFork, cudaEventDisableTiming);
        cudaEventCreateWithFlags(&evS2,   cudaEventDisableTiming);
    }

    const float* feat_word  = (const float*)d_in[0];
    const float* feat_topic = (const float*)d_in[1];

    // Edge sets in CSR order: ww, wt, tt, wd, td.
    ES es;
    es.src[0] = (const int*)d_in[2];  es.dst[0] = (const int*)d_in[3];
    es.w[0] = (const float*)d_in[4];  es.E[0] = in_sizes[2];  es.base[0] = DEG_WW;
    es.src[1] = (const int*)d_in[5];  es.dst[1] = (const int*)d_in[6];
    es.w[1] = (const float*)d_in[7];  es.E[1] = in_sizes[5];  es.base[1] = DEG_WT;
    es.src[2] = (const int*)d_in[14]; es.dst[2] = (const int*)d_in[15];
    es.w[2] = (const float*)d_in[16]; es.E[2] = in_sizes[14]; es.base[2] = DEG_TT;
    es.src[3] = (const int*)d_in[8];  es.dst[3] = (const int*)d_in[9];
    es.w[3] = (const float*)d_in[10]; es.E[3] = in_sizes[8];  es.base[3] = DEG_WD;
    es.src[4] = (const int*)d_in[11]; es.dst[4] = (const int*)d_in[12];
    es.w[4] = (const float*)d_in[13]; es.E[4] = in_sizes[11]; es.base[4] = DEG_TD;
    int totalE = es.E[0] + es.E[1] + es.E[2] + es.E[3] + es.E[4];
    int strideE = (totalE + 3) / 4;   // 4 edges per thread

    const float* W_ww = (const float*)d_in[17]; const float* b_ww = (const float*)d_in[18];
    const float* W_wt = (const float*)d_in[19]; const float* b_wt = (const float*)d_in[20];
    const float* W_wd = (const float*)d_in[21]; const float* b_wd = (const float*)d_in[22];
    const float* W_td = (const float*)d_in[23]; const float* b_td = (const float*)d_in[24];
    const float* W_tt = (const float*)d_in[25]; const float* b_tt = (const float*)d_in[26];

    float* out = (float*)d_out;

    float* p_ww; cudaGetSymbolAddress((void**)&p_ww, g_Wh_ww);
    float* p_wt; cudaGetSymbolAddress((void**)&p_wt, g_Wh_wt);
    float* p_wd; cudaGetSymbolAddress((void**)&p_wd, g_Wh_wd);
    float* p_td; cudaGetSymbolAddress((void**)&p_td, g_Wh_td);
    float* p_tt; cudaGetSymbolAddress((void**)&p_tt, g_Wh_tt);

    // ---- Fork s2 from the capture (legacy) stream. ----
    cudaEventRecord(evFork, 0);
    cudaStreamWaitEvent(s2, evFork, 0);

    // ---- s2: CSR build, then the tiny topic GEMM (concurrent w/ G_words). --
    zero_cnt<<<(NDEG + 255) / 256, 256, 0, s2>>>();
    hist_all<<<(strideE + 255) / 256, 256, 0, s2>>>(es, totalE, strideE);
    scan1<<<NSCAN, 256, 0, s2>>>();
    scan2<<<1, 256, 0, s2>>>();
    scan3<<<(NDEG + 255) / 256, 256, 0, s2>>>();
    permute_all<<<(strideE + 255) / 256, 256, 0, s2>>>(es, totalE, strideE);
    {
        int gt = (NT + 127) / 128;   // 16 -> y=2: 32 CTAs
        gemm_bf16<128><<<dim3(gt, 2), 256, 0, s2>>>(feat_topic,
                                                    W_tt, b_tt, p_tt,
                                                    W_td, b_td, p_td,
                                                    W_td, b_td, p_td, NT);
    }
    cudaEventRecord(evS2, s2);

    // ---- legacy: word projections (1173 CTAs, ~4 full waves). ----
    {
        int gw = (NW + 127) / 128;   // 391
        gemm_bf16<DW><<<dim3(gw, 3), 256>>>(feat_word,
                                            W_ww, b_ww, p_ww,
                                            W_wt, b_wt, p_wt,
                                            W_wd, b_wd, p_wd, NW);
    }

    // ---- legacy: fused aggregation over ALL output rows. ----
    cudaStreamWaitEvent(0, evS2, 0);
    agg_all<<<(NROWS + 7) / 8, 256>>>(p_ww, p_wt, p_tt, p_wd, p_td, out);
}